// round 8
// baseline (speedup 1.0000x reference)
#include <cuda_runtime.h>
#include <cuda_bf16.h>

#define NBINS 100
#define ROWS  100          // floor rows 0..99
#define EPSF  1e-10f
#define GRID_BLOCKS 608    // 152 SMs * 4 blocks (51.2KB table each)
#define DEPTH 8            // float4-pairs in flight per thread
#define SMEM_BYTES (ROWS * 32 * 16)

// Per-row global partials: C=(1-fr)w sums, B=fr*w sums, and their squares.
__device__ float        gC[ROWS], gB[ROWS], gC2[ROWS], gB2[ROWS];
__device__ unsigned int g_count;

struct C4 { int j; float c, b, c2, b2; };

// One RMW location per element: everything lands at floor row j.
// Readout shift implements the reference validity masks exactly.
__device__ __forceinline__ C4 mk(float of, float wf, float invd, float nb0) {
    C4 r;
    float t  = fmaf(of, invd, nb0);     // (of - b0) * invd  (>= 0 for valid data)
    float jf = floorf(t);
    float fr = t - jf;
    int j = (int)jf;
    r.j  = min(max(j, 0), ROWS - 1);    // clamp rows pool junk into masked rows
    r.b  = fr * wf;                     // ws  -> read at bin j+1
    r.c  = wf - r.b;                    // wp  -> read at bin j
    r.c2 = r.c * r.c;
    r.b2 = r.b * r.b;
    return r;
}

// Two elements: both LDS.128 up front; single equality merge; ordered stores.
__device__ __forceinline__ void pair_rmw(float4* __restrict__ shl, C4 a, C4 b) {
    float4* pa = shl + a.j * 32;
    float4* pb = shl + b.j * 32;
    float4 la = *pa;
    float4 lb = *pb;
    bool eq = (a.j == b.j);
    float fc  = eq ? a.c  : 0.0f;
    float fb  = eq ? a.b  : 0.0f;
    float fc2 = eq ? a.c2 : 0.0f;
    float fb2 = eq ? a.b2 : 0.0f;
    la.x += a.c;      la.y += a.b;      la.z += a.c2;      la.w += a.b2;
    lb.x += b.c + fc; lb.y += b.b + fb; lb.z += b.c2 + fc2; lb.w += b.b2 + fb2;
    *pa = la;
    *pb = lb;     // stored last: on eq the fully-merged value wins
}

__device__ __forceinline__ void process4(float4* __restrict__ shl,
                                         float4 o, float4 w,
                                         float invd, float nb0)
{
    C4 c0 = mk(o.x, w.x, invd, nb0);
    C4 c1 = mk(o.y, w.y, invd, nb0);
    C4 c2 = mk(o.z, w.z, invd, nb0);
    C4 c3 = mk(o.w, w.w, invd, nb0);
    pair_rmw(shl, c0, c1);
    pair_rmw(shl, c2, c3);
}

__global__ __launch_bounds__(32) void fused_k(
    const float4* __restrict__ obs4,
    const float4* __restrict__ wts4,
    const float*  __restrict__ obs_s,
    const float*  __restrict__ wts_s,
    const float*  __restrict__ bins,
    const float*  __restrict__ histo_exp,
    float*        __restrict__ out,
    int nvec, int n)
{
    extern __shared__ float4 sh[];      // [ROWS][32] cells (c, b, c2, b2)
    const int lane = threadIdx.x;

    for (int i = lane; i < ROWS * 32; i += 32)
        sh[i] = make_float4(0.0f, 0.0f, 0.0f, 0.0f);
    __syncwarp();

    const float b0   = __ldg(&bins[0]);
    const float bN   = __ldg(&bins[NBINS]);
    const float invd = (float)NBINS / (bN - b0);
    const float nb0  = -b0 * invd;

    float4* shl = &sh[lane];
    const int stride = GRID_BLOCKS * 32;
    const int base   = blockIdx.x * 32 + lane;

    // Deep rotating prefetch pipeline; OOB slots: clamped index + zero weight.
    float4 O[DEPTH], W[DEPTH];
    #pragma unroll
    for (int d = 0; d < DEPTH; d++) {
        int vi   = base + d * stride;
        bool act = vi < nvec;
        int idx  = act ? vi : (nvec - 1);
        O[d] = obs4[idx];
        float4 ww = wts4[idx];
        if (!act) ww = make_float4(0.0f, 0.0f, 0.0f, 0.0f);
        W[d] = ww;
    }

    for (int v = base; v < nvec; v += DEPTH * stride) {
        #pragma unroll
        for (int d = 0; d < DEPTH; d++) {
            int vi   = v + (DEPTH + d) * stride;
            bool act = vi < nvec;
            int idx  = act ? vi : (nvec - 1);
            float4 no = obs4[idx];
            float4 nw = wts4[idx];
            process4(shl, O[d], W[d], invd, nb0);
            O[d] = no;
            W[d] = act ? nw : make_float4(0.0f, 0.0f, 0.0f, 0.0f);
        }
    }

    // Scalar tail (N % 4), block 0 only (empty for N = 2^25).
    if (blockIdx.x == 0) {
        for (int i = nvec * 4 + lane; i < n; i += 32) {
            C4 c = mk(obs_s[i], wts_s[i], invd, nb0);
            float4* p = shl + c.j * 32;
            float4 l = *p;
            l.x += c.c; l.y += c.b; l.z += c.c2; l.w += c.b2;
            *p = l;
        }
    }
    __syncwarp();

    // Rotated conflict-free per-row reduction, 4 global atomics per row.
    #pragma unroll
    for (int g = 0; g < 4; g++) {
        int r = g * 32 + lane;
        if (r < ROWS) {
            float sc = 0.0f, sb = 0.0f, sc2 = 0.0f, sb2 = 0.0f;
            #pragma unroll
            for (int t = 0; t < 32; t++) {
                int c = (lane + t) & 31;
                float4 vv = sh[r * 32 + c];
                sc += vv.x; sb += vv.y; sc2 += vv.z; sb2 += vv.w;
            }
            atomicAdd(&gC[r],  sc);
            atomicAdd(&gB[r],  sb);
            atomicAdd(&gC2[r], sc2);
            atomicAdd(&gB2[r], sb2);
        }
    }

    // Last-block-done: final chi^2 + reset for next graph replay.
    __syncwarp();
    __threadfence();
    unsigned int done = 0;
    if (lane == 0) done = atomicAdd(&g_count, 1u);
    done = __shfl_sync(0xFFFFFFFFu, done, 0);
    if (done == (unsigned)(GRID_BLOCKS - 1)) {
        __threadfence();
        float hs[4], ss[4], he[4];
        float hsum = 0.0f, esum = 0.0f;
        #pragma unroll
        for (int g = 0; g < 4; g++) {
            int d = g * 32 + lane;
            bool inner = (d >= 1) && (d <= NBINS - 2);
            float cC  = inner ? __ldcg(&gC[d])      : 0.0f;
            float cB  = inner ? __ldcg(&gB[d - 1])  : 0.0f;
            float cC2 = inner ? __ldcg(&gC2[d])     : 0.0f;
            float cB2 = inner ? __ldcg(&gB2[d - 1]) : 0.0f;
            hs[g] = cC + cB;
            ss[g] = cC2 + cB2;
            he[g] = (d < NBINS) ? __ldg(&histo_exp[d]) : 0.0f;
            hsum += hs[g];
            esum += he[g];
        }
        #pragma unroll
        for (int o = 16; o > 0; o >>= 1) {
            hsum += __shfl_xor_sync(0xFFFFFFFFu, hsum, o);
            esum += __shfl_xor_sync(0xFFFFFFFFu, esum, o);
        }
        const float inv_ss2 = 1.0f / ((hsum + EPSF) * (hsum + EPSF));
        const float inv_se2 = 1.0f / ((esum + EPSF) * (esum + EPSF));
        const float inv_ss  = 1.0f / hsum;
        const float inv_se  = 1.0f / esum;
        float chi = 0.0f;
        #pragma unroll
        for (int g = 0; g < 4; g++) {
            int d = g * 32 + lane;
            if (d < NBINS) {
                float unc_sim = ss[g] * inv_ss2 + EPSF;
                float unc_exp = he[g] * (1.0f - he[g] * inv_se) * inv_se2 + EPSF;
                float df = hs[g] * inv_ss - he[g] * inv_se;
                chi += df * df / (unc_sim + unc_exp);
            }
        }
        #pragma unroll
        for (int o = 16; o > 0; o >>= 1)
            chi += __shfl_xor_sync(0xFFFFFFFFu, chi, o);
        if (lane == 0) out[0] = chi;

        #pragma unroll
        for (int g = 0; g < 4; g++) {
            int d = g * 32 + lane;
            if (d < ROWS) {
                __stcg(&gC[d],  0.0f);
                __stcg(&gB[d],  0.0f);
                __stcg(&gC2[d], 0.0f);
                __stcg(&gB2[d], 0.0f);
            }
        }
        __threadfence();
        if (lane == 0) atomicExch(&g_count, 0u);
    }
}

extern "C" void kernel_launch(void* const* d_in, const int* in_sizes, int n_in,
                              void* d_out, int out_size) {
    const float* sim  = (const float*)d_in[0];
    // d_in[1] = exp_observable: unused in the fixed_binning branch
    const float* wts  = (const float*)d_in[2];
    const float* bins = (const float*)d_in[3];
    const float* he   = (const float*)d_in[4];
    int n    = in_sizes[0];
    int nvec = n / 4;

    cudaFuncSetAttribute(fused_k, cudaFuncAttributeMaxDynamicSharedMemorySize, SMEM_BYTES);
    cudaFuncSetAttribute(fused_k, cudaFuncAttributePreferredSharedMemoryCarveout, 100);

    fused_k<<<GRID_BLOCKS, 32, SMEM_BYTES>>>((const float4*)sim, (const float4*)wts,
                                             sim, wts, bins, he, (float*)d_out, nvec, n);
}

// round 9
// speedup vs baseline: 1.2352x; 1.2352x over previous
#include <cuda_runtime.h>
#include <cuda_bf16.h>

#define NBINS 100
#define EPSF  1e-10f
#define COLS  32
#define GRID_BLOCKS 1216   // 152 SMs * 8 blocks
#define DEPTH 14           // float4-pairs in flight per thread (28 LDG.128)

__device__ float        g_hist[NBINS];
__device__ float        g_wss[NBINS];
__device__ unsigned int g_count;

struct Contrib {
    int   jc;
    float wp, wpq, ws, wsq;
};

__device__ __forceinline__ Contrib elem_contrib(float of, float wf,
                                                float invd, float nb0)
{
    Contrib c;
    float t  = fmaf(of, invd, nb0);          // (of - b0) * invd
    float jf = floorf(t);
    float fr = t - jf;
    int   j  = (int)jf;
    c.jc     = min(max(j, 0), NBINS - 2);
    bool sub  = ((unsigned)j       <= (unsigned)(NBINS - 3)); // -> bin jc+1
    bool plus = ((unsigned)(j - 1) <= (unsigned)(NBINS - 3)); // -> bin jc
    c.ws  = sub  ? fr * wf           : 0.0f;
    c.wp  = plus ? (1.0f - fr) * wf  : 0.0f;
    c.wsq = c.ws * c.ws;
    c.wpq = c.wp * c.wp;
    return c;
}

// Two elements' RMWs with collision merge so all 4 LDS issue before any STS.
__device__ __forceinline__ void pair_rmw(float2* __restrict__ shl,
                                         Contrib a, Contrib b)
{
    int d = b.jc - a.jc;
    bool m0 = (d == 0), mp = (d == 1), mm = (d == -1);
    float addp  = m0 ? a.wp  : (mp ? a.ws  : 0.0f);
    float addpq = m0 ? a.wpq : (mp ? a.wsq : 0.0f);
    float adds  = m0 ? a.ws  : (mm ? a.wp  : 0.0f);
    float addsq = m0 ? a.wsq : (mm ? a.wpq : 0.0f);
    b.wp  += addp;  b.wpq += addpq;
    b.ws  += adds;  b.wsq += addsq;
    bool za = m0 | mm;
    bool zs = m0 | mp;
    a.wp  = za ? 0.0f : a.wp;   a.wpq = za ? 0.0f : a.wpq;
    a.ws  = zs ? 0.0f : a.ws;   a.wsq = zs ? 0.0f : a.wsq;

    float2 a0 = shl[a.jc * COLS];
    float2 a1 = shl[(a.jc + 1) * COLS];
    float2 b0 = shl[b.jc * COLS];
    float2 b1 = shl[(b.jc + 1) * COLS];
    a0.x += a.wp; a0.y += a.wpq;
    a1.x += a.ws; a1.y += a.wsq;
    b0.x += b.wp; b0.y += b.wpq;
    b1.x += b.ws; b1.y += b.wsq;
    shl[a.jc * COLS]       = a0;
    shl[(a.jc + 1) * COLS] = a1;
    shl[b.jc * COLS]       = b0;
    shl[(b.jc + 1) * COLS] = b1;
}

__device__ __forceinline__ void process4(float2* __restrict__ shl,
                                         float4 o, float4 w,
                                         float invd, float nb0)
{
    Contrib c0 = elem_contrib(o.x, w.x, invd, nb0);
    Contrib c1 = elem_contrib(o.y, w.y, invd, nb0);
    Contrib c2 = elem_contrib(o.z, w.z, invd, nb0);
    Contrib c3 = elem_contrib(o.w, w.w, invd, nb0);
    pair_rmw(shl, c0, c1);
    pair_rmw(shl, c2, c3);
}

__global__ __launch_bounds__(32, 8) void fused_k(
    const float4* __restrict__ obs4,
    const float4* __restrict__ wts4,
    const float*  __restrict__ obs_s,
    const float*  __restrict__ wts_s,
    const float*  __restrict__ bins,
    const float*  __restrict__ histo_exp,
    float*        __restrict__ out,
    int nvec, int n)
{
    __shared__ float2 sh[NBINS * COLS];
    const int lane = threadIdx.x;

    #pragma unroll
    for (int i = lane; i < NBINS * COLS; i += 32)
        sh[i] = make_float2(0.0f, 0.0f);
    __syncwarp();

    const float b0   = __ldg(&bins[0]);
    const float bN   = __ldg(&bins[NBINS]);
    const float invd = (float)NBINS / (bN - b0);
    const float nb0  = -b0 * invd;

    float2* shl = &sh[lane];
    const int stride = GRID_BLOCKS * 32;
    const int base   = blockIdx.x * 32 + lane;

    // Deep rotating prefetch pipeline: DEPTH (obs,wts) float4 pairs in flight.
    // OOB slots load a clamped index (L2 hit) with weights zeroed -> contribute
    // nothing, so every slot is processed unconditionally (branch-free).
    float4 O[DEPTH], W[DEPTH];
    #pragma unroll
    for (int d = 0; d < DEPTH; d++) {
        int vi   = base + d * stride;
        bool act = vi < nvec;
        int idx  = act ? vi : (nvec - 1);
        O[d] = obs4[idx];
        float4 ww = wts4[idx];
        if (!act) ww = make_float4(0.0f, 0.0f, 0.0f, 0.0f);
        W[d] = ww;
    }

    for (int v = base; v < nvec; v += DEPTH * stride) {
        #pragma unroll
        for (int d = 0; d < DEPTH; d++) {
            int vi   = v + (DEPTH + d) * stride;
            bool act = vi < nvec;
            int idx  = act ? vi : (nvec - 1);
            float4 no = obs4[idx];
            float4 nw = wts4[idx];
            process4(shl, O[d], W[d], invd, nb0);
            O[d] = no;
            W[d] = act ? nw : make_float4(0.0f, 0.0f, 0.0f, 0.0f);
        }
    }

    // Scalar tail (N % 4), block 0 only (empty for N = 2^25).
    if (blockIdx.x == 0) {
        for (int i = nvec * 4 + lane; i < n; i += 32) {
            Contrib c = elem_contrib(obs_s[i], wts_s[i], invd, nb0);
            float2 x0 = shl[c.jc * COLS];
            x0.x += c.wp; x0.y += c.wpq;
            shl[c.jc * COLS] = x0;
            float2 x1 = shl[(c.jc + 1) * COLS];
            x1.x += c.ws; x1.y += c.wsq;
            shl[(c.jc + 1) * COLS] = x1;
        }
    }
    __syncwarp();

    // Conflict-free rotated per-bin reduction, then one global atomic per bin.
    #pragma unroll
    for (int g = 0; g < 4; g++) {
        int b = g * 32 + lane;
        if (b < NBINS) {
            float h = 0.0f, s = 0.0f;
            #pragma unroll
            for (int t = 0; t < 32; t++) {
                int c = (lane + t) & 31;
                float2 vv = sh[b * COLS + c];
                h += vv.x; s += vv.y;
            }
            atomicAdd(&g_hist[b], h);
            atomicAdd(&g_wss[b], s);
        }
    }

    // Last-block-done: final chi^2 + reset for next graph replay.
    __syncwarp();
    __threadfence();
    unsigned int done = 0;
    if (lane == 0) done = atomicAdd(&g_count, 1u);
    done = __shfl_sync(0xFFFFFFFFu, done, 0);
    if (done == (unsigned)(GRID_BLOCKS - 1)) {
        __threadfence();
        float hs[4], ss[4], he[4];
        float hsum = 0.0f, esum = 0.0f;
        #pragma unroll
        for (int g = 0; g < 4; g++) {
            int b = g * 32 + lane;
            bool ok = (b < NBINS);
            hs[g] = ok ? __ldcg(&g_hist[b]) : 0.0f;
            ss[g] = ok ? __ldcg(&g_wss[b])  : 0.0f;
            he[g] = ok ? __ldg(&histo_exp[b]) : 0.0f;
            hsum += hs[g];
            esum += he[g];
        }
        #pragma unroll
        for (int o = 16; o > 0; o >>= 1) {
            hsum += __shfl_xor_sync(0xFFFFFFFFu, hsum, o);
            esum += __shfl_xor_sync(0xFFFFFFFFu, esum, o);
        }
        const float inv_ss2 = 1.0f / ((hsum + EPSF) * (hsum + EPSF));
        const float inv_se2 = 1.0f / ((esum + EPSF) * (esum + EPSF));
        const float inv_ss  = 1.0f / hsum;
        const float inv_se  = 1.0f / esum;
        float chi = 0.0f;
        #pragma unroll
        for (int g = 0; g < 4; g++) {
            int b = g * 32 + lane;
            if (b < NBINS) {
                float unc_sim = ss[g] * inv_ss2 + EPSF;
                float unc_exp = he[g] * (1.0f - he[g] * inv_se) * inv_se2 + EPSF;
                float d = hs[g] * inv_ss - he[g] * inv_se;
                chi += d * d / (unc_sim + unc_exp);
            }
        }
        #pragma unroll
        for (int o = 16; o > 0; o >>= 1)
            chi += __shfl_xor_sync(0xFFFFFFFFu, chi, o);
        if (lane == 0) out[0] = chi;

        #pragma unroll
        for (int g = 0; g < 4; g++) {
            int b = g * 32 + lane;
            if (b < NBINS) {
                __stcg(&g_hist[b], 0.0f);
                __stcg(&g_wss[b], 0.0f);
            }
        }
        __threadfence();
        if (lane == 0) atomicExch(&g_count, 0u);
    }
}

extern "C" void kernel_launch(void* const* d_in, const int* in_sizes, int n_in,
                              void* d_out, int out_size) {
    const float* sim  = (const float*)d_in[0];
    // d_in[1] = exp_observable: unused in the fixed_binning branch
    const float* wts  = (const float*)d_in[2];
    const float* bins = (const float*)d_in[3];
    const float* he   = (const float*)d_in[4];
    int n    = in_sizes[0];
    int nvec = n / 4;

    cudaFuncSetAttribute(fused_k, cudaFuncAttributePreferredSharedMemoryCarveout, 100);

    fused_k<<<GRID_BLOCKS, 32>>>((const float4*)sim, (const float4*)wts,
                                 sim, wts, bins, he, (float*)d_out, nvec, n);
}

// round 10
// speedup vs baseline: 1.2671x; 1.0259x over previous
#include <cuda_runtime.h>
#include <cuda_bf16.h>

#define NBINS 100
#define NROWS 102          // guard rows: j in [0,100] -> rows j and j+1; bins = rows 1..98
#define EPSF  1e-10f
#define GRID_BLOCKS 2432   // 152 SMs * 16 blocks (13KB bf16x2 table each)
#define DEPTH 8            // float4-pairs in flight per thread

__device__ float        g_hist[NBINS];
__device__ float        g_wss[NBINS];
__device__ unsigned int g_count;

typedef unsigned int u32;

// pack (low = w, high = w^2) as bf16x2
__device__ __forceinline__ u32 packbf(float w, float wsq) {
    u32 r; asm("cvt.rn.bf16x2.f32 %0, %1, %2;" : "=r"(r) : "f"(wsq), "f"(w)); return r;
}
__device__ __forceinline__ u32 baddx2(u32 a, u32 b) {
    u32 r; asm("add.rn.bf16x2 %0, %1, %2;" : "=r"(r) : "r"(a), "r"(b)); return r;
}
__device__ __forceinline__ float bf_lo(u32 u) { return __uint_as_float(u << 16); }
__device__ __forceinline__ float bf_hi(u32 u) { return __uint_as_float(u & 0xFFFF0000u); }

// One element: two RMWs at rows j and j+1 (compiler-visibly disjoint -> parallel).
// No validity predicates: guard rows absorb edge cases; readout masks rows 1..98.
__device__ __forceinline__ void process_elem(u32* __restrict__ shl,
                                             float of, float wf,
                                             float invd, float nb0)
{
    float t  = fmaf(of, invd, nb0);     // (of - b0) * invd, in [0,100] for valid data
    float jf = floorf(t);
    float fr = t - jf;
    int j = (int)jf;
    j = min(max(j, 0), NROWS - 2);      // 0..100
    float frw = fr * wf;                // ws -> row j+1
    float wp  = wf - frw;               // wp -> row j
    u32 P = packbf(wp,  wp * wp);
    u32 S = packbf(frw, frw * frw);
    u32 u0 = shl[j * 32];
    u32 u1 = shl[(j + 1) * 32];
    u0 = baddx2(u0, P);
    u1 = baddx2(u1, S);
    shl[j * 32]       = u0;
    shl[(j + 1) * 32] = u1;
}

__device__ __forceinline__ void process4(u32* __restrict__ shl,
                                         float4 o, float4 w,
                                         float invd, float nb0)
{
    process_elem(shl, o.x, w.x, invd, nb0);
    process_elem(shl, o.y, w.y, invd, nb0);
    process_elem(shl, o.z, w.z, invd, nb0);
    process_elem(shl, o.w, w.w, invd, nb0);
}

__global__ __launch_bounds__(32, 16) void fused_k(
    const float4* __restrict__ obs4,
    const float4* __restrict__ wts4,
    const float*  __restrict__ obs_s,
    const float*  __restrict__ wts_s,
    const float*  __restrict__ bins,
    const float*  __restrict__ histo_exp,
    float*        __restrict__ out,
    int nvec, int n)
{
    __shared__ u32 sh[NROWS * 32];   // cell = bf16x2 (hist lo, wss hi); stride 128B: bank = lane
    const int lane = threadIdx.x;

    #pragma unroll
    for (int i = lane; i < NROWS * 32; i += 32)
        sh[i] = 0u;
    __syncwarp();

    const float b0   = __ldg(&bins[0]);
    const float bN   = __ldg(&bins[NBINS]);
    const float invd = (float)NBINS / (bN - b0);
    const float nb0  = -b0 * invd;

    u32* shl = &sh[lane];
    const int stride = GRID_BLOCKS * 32;
    const int base   = blockIdx.x * 32 + lane;

    // Deep rotating prefetch pipeline; OOB slots: clamped index + zero weight.
    float4 O[DEPTH], W[DEPTH];
    #pragma unroll
    for (int d = 0; d < DEPTH; d++) {
        int vi   = base + d * stride;
        bool act = vi < nvec;
        int idx  = act ? vi : (nvec - 1);
        O[d] = obs4[idx];
        float4 ww = wts4[idx];
        if (!act) ww = make_float4(0.0f, 0.0f, 0.0f, 0.0f);
        W[d] = ww;
    }

    for (int v = base; v < nvec; v += DEPTH * stride) {
        #pragma unroll
        for (int d = 0; d < DEPTH; d++) {
            int vi   = v + (DEPTH + d) * stride;
            bool act = vi < nvec;
            int idx  = act ? vi : (nvec - 1);
            float4 no = obs4[idx];
            float4 nw = wts4[idx];
            process4(shl, O[d], W[d], invd, nb0);
            O[d] = no;
            W[d] = act ? nw : make_float4(0.0f, 0.0f, 0.0f, 0.0f);
        }
    }

    // Scalar tail (N % 4), block 0 only (empty for N = 2^25).
    if (blockIdx.x == 0) {
        for (int i = nvec * 4 + lane; i < n; i += 32)
            process_elem(shl, obs_s[i], wts_s[i], invd, nb0);
    }
    __syncwarp();

    // Rotated conflict-free per-row reduction in fp32; rows 1..98 are real bins.
    #pragma unroll
    for (int g = 0; g < 4; g++) {
        int r = g * 32 + lane;
        if (r >= 1 && r <= NBINS - 2) {
            float h = 0.0f, s = 0.0f;
            #pragma unroll
            for (int t = 0; t < 32; t++) {
                int c = (lane + t) & 31;
                u32 u = sh[r * 32 + c];
                h += bf_lo(u);
                s += bf_hi(u);
            }
            atomicAdd(&g_hist[r], h);
            atomicAdd(&g_wss[r], s);
        }
    }

    // Last-block-done: final chi^2 + reset for next graph replay.
    __syncwarp();
    __threadfence();
    unsigned int done = 0;
    if (lane == 0) done = atomicAdd(&g_count, 1u);
    done = __shfl_sync(0xFFFFFFFFu, done, 0);
    if (done == (unsigned)(GRID_BLOCKS - 1)) {
        __threadfence();
        float hs[4], ss[4], he[4];
        float hsum = 0.0f, esum = 0.0f;
        #pragma unroll
        for (int g = 0; g < 4; g++) {
            int b = g * 32 + lane;
            bool ok = (b < NBINS);
            hs[g] = ok ? __ldcg(&g_hist[b]) : 0.0f;
            ss[g] = ok ? __ldcg(&g_wss[b])  : 0.0f;
            he[g] = ok ? __ldg(&histo_exp[b]) : 0.0f;
            hsum += hs[g];
            esum += he[g];
        }
        #pragma unroll
        for (int o = 16; o > 0; o >>= 1) {
            hsum += __shfl_xor_sync(0xFFFFFFFFu, hsum, o);
            esum += __shfl_xor_sync(0xFFFFFFFFu, esum, o);
        }
        const float inv_ss2 = 1.0f / ((hsum + EPSF) * (hsum + EPSF));
        const float inv_se2 = 1.0f / ((esum + EPSF) * (esum + EPSF));
        const float inv_ss  = 1.0f / hsum;
        const float inv_se  = 1.0f / esum;
        float chi = 0.0f;
        #pragma unroll
        for (int g = 0; g < 4; g++) {
            int b = g * 32 + lane;
            if (b < NBINS) {
                float unc_sim = ss[g] * inv_ss2 + EPSF;
                float unc_exp = he[g] * (1.0f - he[g] * inv_se) * inv_se2 + EPSF;
                float d = hs[g] * inv_ss - he[g] * inv_se;
                chi += d * d / (unc_sim + unc_exp);
            }
        }
        #pragma unroll
        for (int o = 16; o > 0; o >>= 1)
            chi += __shfl_xor_sync(0xFFFFFFFFu, chi, o);
        if (lane == 0) out[0] = chi;

        #pragma unroll
        for (int g = 0; g < 4; g++) {
            int b = g * 32 + lane;
            if (b < NBINS) {
                __stcg(&g_hist[b], 0.0f);
                __stcg(&g_wss[b], 0.0f);
            }
        }
        __threadfence();
        if (lane == 0) atomicExch(&g_count, 0u);
    }
}

extern "C" void kernel_launch(void* const* d_in, const int* in_sizes, int n_in,
                              void* d_out, int out_size) {
    const float* sim  = (const float*)d_in[0];
    // d_in[1] = exp_observable: unused in the fixed_binning branch
    const float* wts  = (const float*)d_in[2];
    const float* bins = (const float*)d_in[3];
    const float* he   = (const float*)d_in[4];
    int n    = in_sizes[0];
    int nvec = n / 4;

    cudaFuncSetAttribute(fused_k, cudaFuncAttributePreferredSharedMemoryCarveout, 100);

    fused_k<<<GRID_BLOCKS, 32>>>((const float4*)sim, (const float4*)wts,
                                 sim, wts, bins, he, (float*)d_out, nvec, n);
}

// round 11
// speedup vs baseline: 1.6092x; 1.2699x over previous
#include <cuda_runtime.h>
#include <cuda_bf16.h>
#include <cstdint>

#define NBINS 100
#define NROWS 102            // guard rows; real bins are rows 1..98
#define EPSF  1e-10f
#define NWARP 4
#define THREADS 128
#define GRID_BLOCKS 304      // 152 SMs * 2 blocks
#define NSTAGES 3
#define CHUNK_ELEMS 2048
#define CHUNK_BYTES (CHUNK_ELEMS * 4)              // 8192 per array
#define TABLE_U32   (NROWS * 32)                   // per-warp table words
#define SMEM_TABLE  0
#define SMEM_OBS    (NWARP * TABLE_U32 * 4)        // 52224
#define SMEM_WTS    (SMEM_OBS + NSTAGES * CHUNK_BYTES)
#define SMEM_MBAR   (SMEM_WTS + NSTAGES * CHUNK_BYTES)
#define SMEM_TOTAL  (SMEM_MBAR + NSTAGES * 8 + 8)

__device__ float        g_hist[NBINS];
__device__ float        g_wss[NBINS];
__device__ unsigned int g_count;

typedef unsigned int u32;

// ---- bf16x2 cell ops (validated R9: rel_err 3.4e-6) ----
__device__ __forceinline__ u32 packbf(float w, float wsq) {
    u32 r; asm("cvt.rn.bf16x2.f32 %0, %1, %2;" : "=r"(r) : "f"(wsq), "f"(w)); return r;
}
__device__ __forceinline__ u32 baddx2(u32 a, u32 b) {
    u32 r; asm("add.rn.bf16x2 %0, %1, %2;" : "=r"(r) : "r"(a), "r"(b)); return r;
}
__device__ __forceinline__ float bf_lo(u32 u) { return __uint_as_float(u << 16); }
__device__ __forceinline__ float bf_hi(u32 u) { return __uint_as_float(u & 0xFFFF0000u); }

// ---- mbarrier / bulk-async helpers ----
__device__ __forceinline__ void mbar_init(u32 a, u32 cnt) {
    asm volatile("mbarrier.init.shared.b64 [%0], %1;" :: "r"(a), "r"(cnt) : "memory");
}
__device__ __forceinline__ void mbar_expect(u32 a, u32 bytes) {
    asm volatile("mbarrier.arrive.expect_tx.shared.b64 _, [%0], %1;" :: "r"(a), "r"(bytes) : "memory");
}
__device__ __forceinline__ void mbar_wait(u32 a, u32 ph) {
    asm volatile(
        "{\n\t.reg .pred P;\n"
        "WL%=:\n\t"
        "mbarrier.try_wait.parity.acquire.cta.shared::cta.b64 P, [%0], %1, 0x989680;\n\t"
        "@P bra WD%=;\n\t"
        "bra WL%=;\n"
        "WD%=:\n\t}"
        :: "r"(a), "r"(ph) : "memory");
}
__device__ __forceinline__ void bulk_g2s(u32 dst, const void* src, u32 bytes, u32 mbar) {
    asm volatile("cp.async.bulk.shared::cluster.global.mbarrier::complete_tx::bytes [%0], [%1], %2, [%3];"
                 :: "r"(dst), "l"(src), "r"(bytes), "r"(mbar) : "memory");
}
__device__ __forceinline__ void fence_async_shared() {
    asm volatile("fence.proxy.async.shared::cta;" ::: "memory");
}

// One element: two RMWs at rows j, j+1; no predicates (guard rows absorb edges).
__device__ __forceinline__ void process_elem(u32* __restrict__ shl,
                                             float of, float wf,
                                             float invd, float nb0)
{
    float t  = fmaf(of, invd, nb0);
    float jf = floorf(t);
    float fr = t - jf;
    int j = (int)jf;
    j = min(max(j, 0), NROWS - 2);
    float frw = fr * wf;
    float wp  = wf - frw;
    u32 P = packbf(wp,  wp * wp);
    u32 S = packbf(frw, frw * frw);
    u32 u0 = shl[j * 32];
    u32 u1 = shl[(j + 1) * 32];
    shl[j * 32]       = baddx2(u0, P);
    shl[(j + 1) * 32] = baddx2(u1, S);
}

__device__ __forceinline__ void process_chunk(const char* smem, int s,
                                              u32* __restrict__ shl,
                                              int wid, int lane,
                                              float invd, float nb0)
{
    const float4* ob = (const float4*)(smem + SMEM_OBS + s * CHUNK_BYTES) + wid * (CHUNK_ELEMS / NWARP / 4);
    const float4* wb = (const float4*)(smem + SMEM_WTS + s * CHUNK_BYTES) + wid * (CHUNK_ELEMS / NWARP / 4);
    float4 O[4], W[4];
    #pragma unroll
    for (int t = 0; t < 4; t++) { O[t] = ob[t * 32 + lane]; W[t] = wb[t * 32 + lane]; }
    #pragma unroll
    for (int t = 0; t < 4; t++) {
        process_elem(shl, O[t].x, W[t].x, invd, nb0);
        process_elem(shl, O[t].y, W[t].y, invd, nb0);
        process_elem(shl, O[t].z, W[t].z, invd, nb0);
        process_elem(shl, O[t].w, W[t].w, invd, nb0);
    }
}

__global__ __launch_bounds__(THREADS, 2) void fused_k(
    const float* __restrict__ obs,
    const float* __restrict__ wts,
    const float* __restrict__ bins,
    const float* __restrict__ histo_exp,
    float*       __restrict__ out,
    int n)
{
    extern __shared__ char smem[];
    u32* table = (u32*)smem;
    const int tid  = threadIdx.x;
    const int wid  = tid >> 5;
    const int lane = tid & 31;

    // zero tables
    for (int i = tid; i < NWARP * TABLE_U32; i += THREADS)
        table[i] = 0u;

    u32 mb[NSTAGES];
    #pragma unroll
    for (int s = 0; s < NSTAGES; s++)
        mb[s] = (u32)__cvta_generic_to_shared(smem + SMEM_MBAR + s * 8);

    if (tid == 0) {
        #pragma unroll
        for (int s = 0; s < NSTAGES; s++) mbar_init(mb[s], 1);
        fence_async_shared();
    }
    __syncthreads();

    const float b0   = __ldg(&bins[0]);
    const float bN   = __ldg(&bins[NBINS]);
    const float invd = (float)NBINS / (bN - b0);
    const float nb0  = -b0 * invd;

    u32* shl = table + wid * TABLE_U32 + lane;

    const int nchunks = n / CHUNK_ELEMS;
    const int myn = (nchunks > (int)blockIdx.x)
                  ? (nchunks - (int)blockIdx.x + GRID_BLOCKS - 1) / GRID_BLOCKS : 0;

    // prologue: fill the ring
    if (tid == 0) {
        #pragma unroll
        for (int s = 0; s < NSTAGES; s++) {
            if (s < myn) {
                long cid = (long)blockIdx.x + (long)s * GRID_BLOCKS;
                mbar_expect(mb[s], 2 * CHUNK_BYTES);
                bulk_g2s((u32)__cvta_generic_to_shared(smem + SMEM_OBS + s * CHUNK_BYTES),
                         obs + cid * CHUNK_ELEMS, CHUNK_BYTES, mb[s]);
                bulk_g2s((u32)__cvta_generic_to_shared(smem + SMEM_WTS + s * CHUNK_BYTES),
                         wts + cid * CHUNK_ELEMS, CHUNK_BYTES, mb[s]);
            }
        }
    }

    int ph0 = 0, ph1 = 0, ph2 = 0;
    for (int k = 0; k < myn; k++) {
        int s;
        int km = k % NSTAGES;
        if (km == 0)      { s = 0; mbar_wait(mb[0], ph0); ph0 ^= 1; }
        else if (km == 1) { s = 1; mbar_wait(mb[1], ph1); ph1 ^= 1; }
        else              { s = 2; mbar_wait(mb[2], ph2); ph2 ^= 1; }

        process_chunk(smem, s, shl, wid, lane, invd, nb0);
        __syncthreads();   // all warps done reading stage s

        int kn = k + NSTAGES;
        if (tid == 0 && kn < myn) {
            long cid = (long)blockIdx.x + (long)kn * GRID_BLOCKS;
            mbar_expect(mb[s], 2 * CHUNK_BYTES);
            bulk_g2s((u32)__cvta_generic_to_shared(smem + SMEM_OBS + s * CHUNK_BYTES),
                     obs + cid * CHUNK_ELEMS, CHUNK_BYTES, mb[s]);
            bulk_g2s((u32)__cvta_generic_to_shared(smem + SMEM_WTS + s * CHUNK_BYTES),
                     wts + cid * CHUNK_ELEMS, CHUNK_BYTES, mb[s]);
        }
    }

    // tail (n % CHUNK_ELEMS), block 0 warp 0, direct global loads
    if (blockIdx.x == 0 && tid < 32) {
        for (int i = nchunks * CHUNK_ELEMS + lane; i < n; i += 32)
            process_elem(shl, obs[i], wts[i], invd, nb0);
    }
    __syncthreads();

    // per-warp rotated conflict-free reduction of its own table; rows 1..98 = bins
    #pragma unroll
    for (int g = 0; g < 4; g++) {
        int r = g * 32 + lane;
        if (r >= 1 && r <= NBINS - 2) {
            float h = 0.0f, sacc = 0.0f;
            #pragma unroll
            for (int t = 0; t < 32; t++) {
                int c = (lane + t) & 31;
                u32 u = table[wid * TABLE_U32 + r * 32 + c];
                h    += bf_lo(u);
                sacc += bf_hi(u);
            }
            atomicAdd(&g_hist[r], h);
            atomicAdd(&g_wss[r], sacc);
        }
    }
    __syncthreads();
    __threadfence();

    // last-block-done: warp 0 computes chi^2, writes out, resets globals
    if (tid < 32) {
        unsigned int done = 0;
        if (lane == 0) done = atomicAdd(&g_count, 1u);
        done = __shfl_sync(0xFFFFFFFFu, done, 0);
        if (done == (unsigned)(GRID_BLOCKS - 1)) {
            __threadfence();
            float hs[4], ss[4], he[4];
            float hsum = 0.0f, esum = 0.0f;
            #pragma unroll
            for (int g = 0; g < 4; g++) {
                int b = g * 32 + lane;
                bool ok = (b < NBINS);
                hs[g] = ok ? __ldcg(&g_hist[b]) : 0.0f;
                ss[g] = ok ? __ldcg(&g_wss[b])  : 0.0f;
                he[g] = ok ? __ldg(&histo_exp[b]) : 0.0f;
                hsum += hs[g];
                esum += he[g];
            }
            #pragma unroll
            for (int o = 16; o > 0; o >>= 1) {
                hsum += __shfl_xor_sync(0xFFFFFFFFu, hsum, o);
                esum += __shfl_xor_sync(0xFFFFFFFFu, esum, o);
            }
            const float inv_ss2 = 1.0f / ((hsum + EPSF) * (hsum + EPSF));
            const float inv_se2 = 1.0f / ((esum + EPSF) * (esum + EPSF));
            const float inv_ss  = 1.0f / hsum;
            const float inv_se  = 1.0f / esum;
            float chi = 0.0f;
            #pragma unroll
            for (int g = 0; g < 4; g++) {
                int b = g * 32 + lane;
                if (b < NBINS) {
                    float unc_sim = ss[g] * inv_ss2 + EPSF;
                    float unc_exp = he[g] * (1.0f - he[g] * inv_se) * inv_se2 + EPSF;
                    float d = hs[g] * inv_ss - he[g] * inv_se;
                    chi += d * d / (unc_sim + unc_exp);
                }
            }
            #pragma unroll
            for (int o = 16; o > 0; o >>= 1)
                chi += __shfl_xor_sync(0xFFFFFFFFu, chi, o);
            if (lane == 0) out[0] = chi;

            #pragma unroll
            for (int g = 0; g < 4; g++) {
                int b = g * 32 + lane;
                if (b < NBINS) {
                    __stcg(&g_hist[b], 0.0f);
                    __stcg(&g_wss[b], 0.0f);
                }
            }
            __threadfence();
            if (lane == 0) atomicExch(&g_count, 0u);
        }
    }
}

extern "C" void kernel_launch(void* const* d_in, const int* in_sizes, int n_in,
                              void* d_out, int out_size) {
    const float* sim  = (const float*)d_in[0];
    // d_in[1] = exp_observable: unused in the fixed_binning branch
    const float* wts  = (const float*)d_in[2];
    const float* bins = (const float*)d_in[3];
    const float* he   = (const float*)d_in[4];
    int n = in_sizes[0];

    cudaFuncSetAttribute(fused_k, cudaFuncAttributeMaxDynamicSharedMemorySize, SMEM_TOTAL);
    cudaFuncSetAttribute(fused_k, cudaFuncAttributePreferredSharedMemoryCarveout, 100);

    fused_k<<<GRID_BLOCKS, THREADS, SMEM_TOTAL>>>(sim, wts, bins, he, (float*)d_out, n);
}